// round 9
// baseline (speedup 1.0000x reference)
#include <cuda_runtime.h>

#define B        1024
#define NUM_VARS 2048
#define LEAVES   4096
#define LEVELS   12
#define WIDTH    4096
#define NINT     (LEVELS * WIDTH)          // 49152
#define TOTAL    (LEAVES + NINT)           // 53248

#define NTHR     512
#define BBK      8                  // batch columns per block (= forward warps)
#define NBLK     (B / BBK)          // 128 blocks

#define PCAP     1536               // max plan nodes on the fast path
#define HSZ      4096               // hash slots (power of two)
#define VPAD     9                  // val stride (9 coprime 32 -> conflict-free)
#define XPAD     2052               // xrow stride in floats (16B aligned)

// Dense-fallback value buffer (touched only if plan exceeds PCAP).
__device__ float g_dense[(size_t)NINT * B];

// ---- smem layout (bytes) ----
#define SM_PCH   0                               // int4[PCAP]  raw children   24576
#define SM_SCH   (SM_PCH + PCAP * 16)            // int2[PCAP]  sorted plan    12288
#define SM_XROW  (SM_SCH + PCAP * 8)             // float[8*XPAD]              65664
#define SM_VAL   (SM_XROW + BBK * XPAD * 4)      // float[PCAP*VPAD]           55296
#define SM_HKEY  (SM_VAL + PCAP * VPAD * 4)      // int[HSZ]                   16384
#define SM_HVAL  (SM_HKEY + HSZ * 4)             // ushort[HSZ]                 8192
#define SM_PORIG (SM_HVAL + HSZ * 2)             // int[PCAP]                   6144
#define SM_META  (SM_PORIG + PCAP * 4)           // int[PCAP] level<<16|rank    6144
#define SM_SCID  (SM_META + PCAP * 4)            // ushort[PCAP]                3072
#define SM_TOTAL (SM_SCID + PCAP * 2)            // 197,760 B

// Named barrier 3: discovery warp (warp 0) + helper warps (8-15) = 288 threads.
#define BAR3() asm volatile("bar.sync 3, 288;" ::: "memory")

__global__ void __launch_bounds__(NTHR, 1)
eval_all(const float* __restrict__ x,
         const int*   __restrict__ child_idx,
         const int*   __restrict__ op_type,
         float*       __restrict__ out)
{
    extern __shared__ unsigned char sm[];
    int4*           pch   = (int4*)          (sm + SM_PCH);
    int2*           sch   = (int2*)          (sm + SM_SCH);
    float*          xrow  = (float*)         (sm + SM_XROW);
    float*          val   = (float*)         (sm + SM_VAL);
    int*            hkey  = (int*)           (sm + SM_HKEY);
    unsigned short* hval  = (unsigned short*)(sm + SM_HVAL);
    int*            porig = (int*)           (sm + SM_PORIG);
    int*            meta  = (int*)           (sm + SM_META);
    unsigned short* scid  = (unsigned short*)(sm + SM_SCID);

    __shared__ int scnt, sFail, sE, sF;
    __shared__ int slcnt[LEVELS], soff[LEVELS + 1];

    const int tid = threadIdx.x;
    const int blk = blockIdx.x;

    if (tid < 32) {
        // ================= warp 0: single-warp BFS discovery =================
        const int lane = tid;
        if (lane < LEVELS) slcnt[lane] = (lane == LEVELS - 1) ? 1 : 0;
        if (lane == 0) {
            scnt = 1; sFail = 0;
            porig[0] = TOTAL - 1;                 // root = cid 0 (never a child)
            meta[0]  = ((LEVELS - 1) << 16);
        }
        BAR3();                                   // hash table initialized
        __syncwarp();

        int s = 0, e = 1;
        while (s < e) {
            for (int base = s; base < e; base += 128) {
                // batch up to 4 frontier entries per lane for LDG MLP
                int  gi[4]; int4 cv[4]; bool act[4];
                #pragma unroll
                for (int q = 0; q < 4; ++q) {
                    const int i = base + lane + q * 32;
                    act[q] = (i < e);
                    if (act[q]) {
                        gi[q] = porig[i];
                        cv[q] = ((const int4*)child_idx)[gi[q] - LEAVES];
                        pch[i] = cv[q];
                    }
                }
                #pragma unroll
                for (int q = 0; q < 4; ++q) {
                    if (!act[q]) continue;
                    const int cs[4] = {cv[q].x, cv[q].y, cv[q].z, cv[q].w};
                    #pragma unroll
                    for (int f = 0; f < 4; ++f) {
                        const int c = cs[f];
                        if (c < LEAVES) continue;
                        unsigned slot = ((unsigned)c * 2654435761u) & (HSZ - 1);
                        while (true) {
                            const int old = atomicCAS(&hkey[slot], -1, c);
                            if (old == -1) {              // claimed: new node
                                const int cid = atomicAdd(&scnt, 1);
                                if (cid < PCAP) {
                                    porig[cid] = c;
                                    const int l2 = (c - LEAVES) >> 12;
                                    const int r2 = atomicAdd(&slcnt[l2], 1);
                                    meta[cid] = (l2 << 16) | r2;
                                    hval[slot] = (unsigned short)cid;
                                } else sFail = 1;
                                break;
                            }
                            if (old == c) break;          // duplicate
                            slot = (slot + 1) & (HSZ - 1);
                        }
                    }
                }
            }
            __syncwarp();
            s = e;
            const int sc = scnt;
            e = (sc < PCAP) ? sc : PCAP;
            if (sFail) break;
        }
        __syncwarp();
        if (lane == 0) {                          // level prefix offsets
            int o = 0;
            for (int l = 0; l < LEVELS; ++l) { soff[l] = o; o += slcnt[l]; }
            soff[LEVELS] = o;
            sE = (scnt < PCAP) ? scnt : PCAP;
            sF = sFail;
        }
    } else if (tid >= 256) {
        // ============ warps 8-15: init hash, then stage x rows ============
        for (int i = tid - 256; i < HSZ; i += 256) hkey[i] = -1;
        BAR3();                                   // release discovery warp
        for (int idx = tid - 256; idx < (BBK * NUM_VARS) / 4; idx += 256) {
            const int r  = idx >> 9;              // /512 float4 per row
            const int c4 = idx & 511;
            const float4 v =
                ((const float4*)x)[(size_t)(blk * BBK + r) * (NUM_VARS / 4) + c4];
            *(float4*)&xrow[r * XPAD + c4 * 4] = v;
        }
    }
    // warps 1-7 fall straight through
    __syncthreads();                              // JOIN: plan + xrow ready

    if (sF) {
        // =============== dense fallback (worst case only) ===============
        for (int l = 0; l < LEVELS; ++l) {
            for (int k = tid; k < WIDTH * BBK; k += NTHR) {
                const int w2 = k >> 3, b2 = k & 7, bg2 = blk * BBK + b2;
                const int ni = l * WIDTH + w2;
                const int4 ch = ((const int4*)child_idx)[ni];
                const int cs[4] = {ch.x, ch.y, ch.z, ch.w};
                float v[4];
                #pragma unroll
                for (int f = 0; f < 4; ++f) {
                    const int c = cs[f];
                    if (c < LEAVES) {
                        const float xv = xrow[b2 * XPAD + (c & (NUM_VARS - 1))];
                        v[f] = (c < NUM_VARS) ? xv : 1.0f - xv;
                    } else {
                        v[f] = g_dense[(size_t)(c - LEAVES) * B + bg2];
                    }
                }
                const float r = op_type[ni] ? (v[0] + v[1]) + (v[2] + v[3])
                                            : (v[0] * v[1]) * (v[2] * v[3]);
                g_dense[(size_t)ni * B + bg2] = r;
            }
            __syncthreads();
        }
        if (tid < BBK)
            out[blk * BBK + tid] = g_dense[(size_t)(NINT - 1) * B + blk * BBK + tid];
        return;
    }

    // ---- resolution: encode + scatter into level-sorted plan (all 512) ----
    // 16-bit operand: bit15=leaf, bits0-11=leaf id or cid; op in bit14 of f0.
    const int n = sE;
    for (int i = tid; i < n; i += NTHR) {
        const int4 ch = pch[i];
        const int mt = meta[i];
        const int j  = soff[mt >> 16] + (mt & 0xFFFF);
        const int op = op_type[porig[i] - LEAVES];
        unsigned f[4];
        const int cs[4] = {ch.x, ch.y, ch.z, ch.w};
        #pragma unroll
        for (int q = 0; q < 4; ++q) {
            const int c = cs[q];
            if (c < LEAVES) f[q] = 0x8000u | (unsigned)c;
            else {
                unsigned slot = ((unsigned)c * 2654435761u) & (HSZ - 1);
                while (hkey[slot] != c) slot = (slot + 1) & (HSZ - 1);
                f[q] = hval[slot];
            }
        }
        f[0] |= ((unsigned)op & 1u) << 14;
        sch[j]  = make_int2((int)(f[0] | (f[1] << 16)), (int)(f[2] | (f[3] << 16)));
        scid[j] = (unsigned short)i;
    }
    __syncthreads();                              // plan finalized

    // ====== forward: warp-per-batch-column, NO block barriers ======
    if (tid < BBK * 32) {
        const int w    = tid >> 5;                // batch column = warp id
        const int lane = tid & 31;
        for (int l = 0; l < LEVELS; ++l) {
            const int e0 = soff[l + 1];
            for (int j = soff[l] + lane; j < e0; j += 32) {
                const int2 e = sch[j];
                const unsigned f0 = (unsigned)e.x & 0xFFFFu;
                const unsigned f1 = (unsigned)e.x >> 16;
                const unsigned f2 = (unsigned)e.y & 0xFFFFu;
                const unsigned f3 = (unsigned)e.y >> 16;
                const int op = (f0 >> 14) & 1;
                #define FETCH(ff) (((ff) & 0x8000u)                               \
                    ? (((ff) & 2048u)                                             \
                        ? 1.0f - xrow[w * XPAD + (int)((ff) & 2047u)]             \
                        :        xrow[w * XPAD + (int)((ff) & 2047u)])            \
                    : val[(int)((ff) & 0xFFFu) * VPAD + w])
                const float v0 = FETCH(f0 & 0x8FFFu);
                const float v1 = FETCH(f1);
                const float v2 = FETCH(f2);
                const float v3 = FETCH(f3);
                #undef FETCH
                const float r = op ? (v0 + v1) + (v2 + v3)
                                   : (v0 * v1) * (v2 * v3);
                val[(int)scid[j] * VPAD + w] = r;
            }
            __syncwarp();                         // intra-warp level ordering
        }
        if (lane == 0) out[blk * BBK + w] = val[w];   // root cid = 0
    }
}

// ---------------------------------------------------------------------------
// Launch: x (f32), child_idx (i32), op_type (i32). One kernel; capturable.
// ---------------------------------------------------------------------------
extern "C" void kernel_launch(void* const* d_in, const int* in_sizes, int n_in,
                              void* d_out, int out_size) {
    const float* x         = (const float*)d_in[0];
    const int*   child_idx = (const int*)  d_in[1];
    const int*   op_type   = (const int*)  d_in[2];
    float*       out       = (float*)d_out;

    cudaFuncSetAttribute(eval_all,
                         cudaFuncAttributeMaxDynamicSharedMemorySize, SM_TOTAL);
    eval_all<<<NBLK, NTHR, SM_TOTAL>>>(x, child_idx, op_type, out);
}

// round 10
// speedup vs baseline: 1.2800x; 1.2800x over previous
#include <cuda_runtime.h>

#define B        1024
#define NUM_VARS 2048
#define LEAVES   4096
#define LEVELS   12
#define WIDTH    4096
#define NINT     (LEVELS * WIDTH)          // 49152
#define TOTAL    (LEAVES + NINT)           // 53248

#define NTHR     512
#define BBK      8                  // batch columns per block (= forward warps)
#define NBLK     (B / BBK)          // 128 blocks
#define NDISC    384                // discovery threads (warps 0-11)

#define PCAP     1536               // max plan nodes on the fast path
#define HSZ      4096               // hash slots (power of two)
#define VPAD     9                  // val stride (9 coprime 32 -> conflict-free)
#define XPAD     2052               // floats; 8208 B row stride (16B aligned)

// Dense-fallback value buffer (touched only if plan exceeds PCAP).
__device__ float g_dense[(size_t)NINT * B];

// ---- smem layout (bytes), 16B alignment where needed ----
#define SM_PCH   0                               // int4[PCAP]   raw children  24576
#define SM_SCH   (SM_PCH + PCAP * 16)            // int2[PCAP]   sorted plan   12288
#define SM_XROW  (SM_SCH + PCAP * 8)             // float[8*XPAD]              65664
#define SM_VAL   (SM_XROW + BBK * XPAD * 4)      // float[PCAP*VPAD]           55296
#define SM_HKEY  (SM_VAL + PCAP * VPAD * 4)      // int[HSZ]                   16384
#define SM_PORIG (SM_HKEY + HSZ * 4)             // int[PCAP]                   6144
#define SM_META  (SM_PORIG + PCAP * 4)           // int[PCAP] level<<16|rank    6144
#define SM_BITS  (SM_META + PCAP * 4)            // uint[NINT/32]               6144
#define SM_HVAL  (SM_BITS + NINT / 8)            // ushort[HSZ]                 8192
#define SM_SCID  (SM_HVAL + HSZ * 2)             // ushort[PCAP]                3072
#define SM_POP   (SM_SCID + PCAP * 2)            // uchar[PCAP]                 1536
#define SM_TOTAL (SM_POP + PCAP)                 // 205,440 B

#define BAR1() asm volatile("bar.sync 1, %0;" :: "n"(NDISC) : "memory")

__global__ void __launch_bounds__(NTHR, 1)
eval_all(const float* __restrict__ x,
         const int*   __restrict__ child_idx,
         const int*   __restrict__ op_type,
         float*       __restrict__ out)
{
    extern __shared__ unsigned char sm[];
    int4*           pch   = (int4*)          (sm + SM_PCH);
    int2*           sch   = (int2*)          (sm + SM_SCH);
    float*          xrow  = (float*)         (sm + SM_XROW);
    float*          val   = (float*)         (sm + SM_VAL);
    int*            hkey  = (int*)           (sm + SM_HKEY);
    int*            porig = (int*)           (sm + SM_PORIG);
    int*            meta  = (int*)           (sm + SM_META);
    unsigned int*   bits  = (unsigned int*)  (sm + SM_BITS);
    unsigned short* hval  = (unsigned short*)(sm + SM_HVAL);
    unsigned short* scid  = (unsigned short*)(sm + SM_SCID);
    unsigned char*  pop   = (unsigned char*) (sm + SM_POP);

    __shared__ int scnt, sE, sF, sFail;
    __shared__ int slcnt[LEVELS], soff[LEVELS + 1];

    const int tid = threadIdx.x;
    const int blk = blockIdx.x;

    if (tid < NDISC) {
        // =============== warps 0-11: worklist-BFS discovery (R8) ===============
        for (int i = tid; i < HSZ; i += NDISC) hkey[i] = -1;
        for (int i = tid; i < NINT / 32; i += NDISC) bits[i] = 0u;
        BAR1();
        if (tid == 0) {
            for (int l = 0; l < LEVELS; ++l) slcnt[l] = 0;
            scnt = 1; sFail = 0;
            porig[0] = TOTAL - 1;                  // root = plan idx (cid) 0
            meta[0]  = (11 << 16) | 0;
            slcnt[11] = 1;
        }
        BAR1();

        int s = 0, e = 1;
        while (s < e) {
            for (int i = s + tid; i < e; i += NDISC) {
                const int ni = porig[i] - LEAVES;
                const int4 ch = ((const int4*)child_idx)[ni];
                pch[i] = ch;
                pop[i] = (unsigned char)op_type[ni];
                const int cs[4] = {ch.x, ch.y, ch.z, ch.w};
                #pragma unroll
                for (int f = 0; f < 4; ++f) {
                    const int c = cs[f];
                    if (c < LEAVES) continue;
                    const int ci = c - LEAVES;
                    const unsigned int m = 1u << (ci & 31);
                    const unsigned int old = atomicOr(&bits[ci >> 5], m);
                    if (!(old & m)) {                         // we claimed c
                        const int cid = atomicAdd(&scnt, 1);
                        if (cid >= PCAP) { sFail = 1; continue; }
                        porig[cid] = c;
                        const int l2 = ci >> 12;              // / WIDTH
                        const int r2 = atomicAdd(&slcnt[l2], 1);
                        meta[cid] = (l2 << 16) | r2;
                        // write-only hash insert (lookups happen post-bar)
                        unsigned slot = ((unsigned)c * 2654435761u) & (HSZ - 1);
                        while (atomicCAS(&hkey[slot], -1, c) != -1)
                            slot = (slot + 1) & (HSZ - 1);
                        hval[slot] = (unsigned short)cid;
                    }
                }
            }
            BAR1();                                   // appends of this wave done
            if (tid == 0) { sE = (scnt < PCAP) ? scnt : PCAP; sF = sFail; }
            BAR1();                                   // snapshot stable
            s = e; e = sE;
            if (sF) break;
        }
    } else {
        // =============== warps 12-15: stage x rows into smem ===============
        for (int idx = tid - NDISC; idx < (BBK * NUM_VARS) / 4; idx += NTHR - NDISC) {
            const int r  = idx >> 9;                  // /512 float4 per row
            const int c4 = idx & 511;
            const float4 v =
                ((const float4*)x)[(size_t)(blk * BBK + r) * (NUM_VARS / 4) + c4];
            *(float4*)&xrow[r * XPAD + c4 * 4] = v;
        }
    }
    __syncthreads();   // join: discovery + staging complete

    if (sF) {
        // =============== dense fallback (worst case only) ===============
        for (int l = 0; l < LEVELS; ++l) {
            for (int k = tid; k < WIDTH * BBK; k += NTHR) {
                const int w2 = k >> 3, b2 = k & 7, bg2 = blk * BBK + b2;
                const int ni = l * WIDTH + w2;
                const int4 ch = ((const int4*)child_idx)[ni];
                const int cs[4] = {ch.x, ch.y, ch.z, ch.w};
                float v[4];
                #pragma unroll
                for (int f = 0; f < 4; ++f) {
                    const int c = cs[f];
                    if (c < LEAVES) {
                        const float xv = xrow[b2 * XPAD + (c & (NUM_VARS - 1))];
                        v[f] = (c < NUM_VARS) ? xv : 1.0f - xv;
                    } else {
                        v[f] = g_dense[(size_t)(c - LEAVES) * B + bg2];
                    }
                }
                const float r = op_type[ni] ? (v[0] + v[1]) + (v[2] + v[3])
                                            : (v[0] * v[1]) * (v[2] * v[3]);
                g_dense[(size_t)ni * B + bg2] = r;
            }
            __syncthreads();
        }
        if (tid < BBK)
            out[blk * BBK + tid] = g_dense[(size_t)(NINT - 1) * B + blk * BBK + tid];
        return;
    }

    // ---- prefix offsets for level-sorted plan ----
    if (tid == 0) {
        int o = 0;
        for (int l = 0; l < LEVELS; ++l) { soff[l] = o; o += slcnt[l]; }
        soff[LEVELS] = o;
    }
    __syncthreads();

    // ---- resolution: encode + scatter entries into level order (all 512) ----
    // 16-bit operand field: bit15 = leaf, bits0-11 = leaf id or cid.
    // op stored in bit14 of field0. Entry's own cid recorded in scid[].
    const int n = sE;
    for (int i = tid; i < n; i += NTHR) {
        const int4 ch = pch[i];
        const int mt = meta[i];
        const int j  = soff[mt >> 16] + (mt & 0xFFFF);
        unsigned f[4];
        const int cs[4] = {ch.x, ch.y, ch.z, ch.w};
        #pragma unroll
        for (int q = 0; q < 4; ++q) {
            const int c = cs[q];
            if (c < LEAVES) f[q] = 0x8000u | (unsigned)c;
            else {
                unsigned slot = ((unsigned)c * 2654435761u) & (HSZ - 1);
                while (hkey[slot] != c) slot = (slot + 1) & (HSZ - 1);
                f[q] = hval[slot];
            }
        }
        f[0] |= ((unsigned)pop[i] & 1u) << 14;
        sch[j]  = make_int2((int)(f[0] | (f[1] << 16)), (int)(f[2] | (f[3] << 16)));
        scid[j] = (unsigned short)i;
    }
    __syncthreads();                              // plan finalized

    // ====== forward (R9): warp-per-batch-column, NO block barriers ======
    if (tid < BBK * 32) {
        const int w    = tid >> 5;                // batch column = warp id
        const int lane = tid & 31;
        for (int l = 0; l < LEVELS; ++l) {
            const int e0 = soff[l + 1];
            for (int j = soff[l] + lane; j < e0; j += 32) {
                const int2 e = sch[j];
                const unsigned f0 = (unsigned)e.x & 0xFFFFu;
                const unsigned f1 = (unsigned)e.x >> 16;
                const unsigned f2 = (unsigned)e.y & 0xFFFFu;
                const unsigned f3 = (unsigned)e.y >> 16;
                const int op = (f0 >> 14) & 1;
                #define FETCH(ff) (((ff) & 0x8000u)                               \
                    ? (((ff) & 2048u)                                             \
                        ? 1.0f - xrow[w * XPAD + (int)((ff) & 2047u)]             \
                        :        xrow[w * XPAD + (int)((ff) & 2047u)])            \
                    : val[(int)((ff) & 0xFFFu) * VPAD + w])
                const float v0 = FETCH(f0 & 0x8FFFu);
                const float v1 = FETCH(f1);
                const float v2 = FETCH(f2);
                const float v3 = FETCH(f3);
                #undef FETCH
                const float r = op ? (v0 + v1) + (v2 + v3)
                                   : (v0 * v1) * (v2 * v3);
                val[(int)scid[j] * VPAD + w] = r;
            }
            __syncwarp();                         // intra-warp level ordering
        }
        if (lane == 0) out[blk * BBK + w] = val[w];   // root cid = 0
    }
}

// ---------------------------------------------------------------------------
// Launch: x (f32), child_idx (i32), op_type (i32). One kernel; capturable.
// ---------------------------------------------------------------------------
extern "C" void kernel_launch(void* const* d_in, const int* in_sizes, int n_in,
                              void* d_out, int out_size) {
    const float* x         = (const float*)d_in[0];
    const int*   child_idx = (const int*)  d_in[1];
    const int*   op_type   = (const int*)  d_in[2];
    float*       out       = (float*)d_out;

    cudaFuncSetAttribute(eval_all,
                         cudaFuncAttributeMaxDynamicSharedMemorySize, SM_TOTAL);
    eval_all<<<NBLK, NTHR, SM_TOTAL>>>(x, child_idx, op_type, out);
}